// round 15
// baseline (speedup 1.0000x reference)
#include <cuda_runtime.h>
#include <cuda_bf16.h>
#include <cstdint>

// x[N=32768, D=2048] fp32 row-major.
// u[d] = sum_n x[n][d]^2 + eps ; out = x * rsqrt(u)
// 3 launches: colsq -> reduce(+rsqrt) -> scale.
// R14 confirmed-best config; single change: KEEP_CHUNK 640 -> 576
// (preserve 112 MB instead of 96 MB of x's tail in L2 for scale reuse).

#define NROWS 32768
#define NCOLS 2048
#define NCOLS4 512                             // float4 column-groups per row
#define ROWS_PER_CHUNK 32
#define ROW_CHUNKS (NROWS / ROWS_PER_CHUNK)    // 1024
#define KEEP_CHUNK 576                         // tail chunks cached normally (112 MB)
#define EPS 1e-6f

// Deterministic scratch (no atomics anywhere)
__device__ float g_part [ROW_CHUNKS * NCOLS];  // 8 MB
__device__ float g_scale[NCOLS];               // 8 KB

// ---------------------------------------------------------------------------
// K1: per-row-chunk column sum of squares. grid = (2, 1024), 32 rows/chunk.
// Early chunks stream (__ldcs, evict-first); tail chunks cached normally for
// scale_kernel's reversed traversal to reuse from L2.
// ---------------------------------------------------------------------------
__global__ void __launch_bounds__(256) colsq_kernel(const float4* __restrict__ x) {
    const int cg    = blockIdx.x * 256 + threadIdx.x;   // 0..511
    const int chunk = blockIdx.y;                        // 0..1023

    const float4* p = x + (size_t)chunk * ROWS_PER_CHUNK * NCOLS4 + cg;

    float ax = 0.f, ay = 0.f, az = 0.f, aw = 0.f;
    if (chunk < KEEP_CHUNK) {
#pragma unroll 8
        for (int r = 0; r < ROWS_PER_CHUNK; ++r) {
            float4 v = __ldcs(p + (size_t)r * NCOLS4);
            ax = fmaf(v.x, v.x, ax);
            ay = fmaf(v.y, v.y, ay);
            az = fmaf(v.z, v.z, az);
            aw = fmaf(v.w, v.w, aw);
        }
    } else {
#pragma unroll 8
        for (int r = 0; r < ROWS_PER_CHUNK; ++r) {
            float4 v = __ldg(p + (size_t)r * NCOLS4);
            ax = fmaf(v.x, v.x, ax);
            ay = fmaf(v.y, v.y, ay);
            az = fmaf(v.z, v.z, az);
            aw = fmaf(v.w, v.w, aw);
        }
    }

    reinterpret_cast<float4*>(g_part)[(size_t)chunk * NCOLS4 + cg] =
        make_float4(ax, ay, az, aw);
}

// ---------------------------------------------------------------------------
// K2: fold 1024 chunk-partials -> scale, high-MLP version (R11/R14).
// 256 CTAs x 8 warps. Each CTA owns 2 column-groups; 4 warps per cg, each
// folding a 256-chunk quarter. Butterfly + smem combine + rsqrt.
// ---------------------------------------------------------------------------
__global__ void __launch_bounds__(256) reduce_kernel() {
    const int w       = threadIdx.x >> 5;        // warp 0..7
    const int lane    = threadIdx.x & 31;
    const int cg_loc  = w >> 2;                  // 0..1: which cg in this CTA
    const int quarter = w & 3;                   // 0..3: chunk quarter
    const int cg      = blockIdx.x * 2 + cg_loc; // 0..511

    const float4* pp = reinterpret_cast<const float4*>(g_part);
    float4 a = make_float4(0.f, 0.f, 0.f, 0.f);
#pragma unroll
    for (int i = 0; i < 8; ++i) {
        const int k = quarter * 256 + i * 32 + lane;
        float4 v = pp[(size_t)k * NCOLS4 + cg];
        a.x += v.x; a.y += v.y; a.z += v.z; a.w += v.w;
    }
#pragma unroll
    for (int off = 16; off > 0; off >>= 1) {
        a.x += __shfl_xor_sync(0xffffffffu, a.x, off);
        a.y += __shfl_xor_sync(0xffffffffu, a.y, off);
        a.z += __shfl_xor_sync(0xffffffffu, a.z, off);
        a.w += __shfl_xor_sync(0xffffffffu, a.w, off);
    }

    __shared__ float4 s_acc[8];                  // one slot per warp
    if (lane == 0) s_acc[w] = a;
    __syncthreads();

    if (threadIdx.x < 2) {                       // one thread per cg
        float4 q0 = s_acc[threadIdx.x * 4 + 0];
        float4 q1 = s_acc[threadIdx.x * 4 + 1];
        float4 q2 = s_acc[threadIdx.x * 4 + 2];
        float4 q3 = s_acc[threadIdx.x * 4 + 3];
        float4 s;
        s.x = rsqrtf(q0.x + q1.x + q2.x + q3.x + EPS);
        s.y = rsqrtf(q0.y + q1.y + q2.y + q3.y + EPS);
        s.z = rsqrtf(q0.z + q1.z + q2.z + q3.z + EPS);
        s.w = rsqrtf(q0.w + q1.w + q2.w + q3.w + EPS);
        reinterpret_cast<float4*>(g_scale)[blockIdx.x * 2 + threadIdx.x] = s;
    }
}

// ---------------------------------------------------------------------------
// K3: out = x * scale[col]. Measured-best form — simple 4-iter loop, plain
// cached loads, streaming stores, reversed block order.
// ---------------------------------------------------------------------------
#define FL4_TOTAL (NROWS * NCOLS4)             // 16M float4
#define FL4_PER_BLOCK 1024
#define K3_BLOCKS (FL4_TOTAL / FL4_PER_BLOCK)  // 16384

__global__ void __launch_bounds__(256) scale_kernel(const float4* __restrict__ x,
                                                    float4* __restrict__ out) {
    const int blk     = K3_BLOCKS - 1 - blockIdx.x;       // reversed
    const size_t base = (size_t)blk * FL4_PER_BLOCK + threadIdx.x;

#pragma unroll
    for (int it = 0; it < 4; ++it) {
        const size_t i  = base + (size_t)it * 256;
        const int    cg = (int)(i & (NCOLS4 - 1));         // NCOLS4=512 pow2

        float4 s = __ldg(reinterpret_cast<const float4*>(g_scale) + cg);
        float4 v = x[i];
        v.x *= s.x; v.y *= s.y; v.z *= s.z; v.w *= s.w;
        __stcs(out + i, v);
    }
}

// ---------------------------------------------------------------------------
extern "C" void kernel_launch(void* const* d_in, const int* in_sizes, int n_in,
                              void* d_out, int out_size) {
    const float4* x   = reinterpret_cast<const float4*>(d_in[0]);
    float4*       out = reinterpret_cast<float4*>(d_out);

    colsq_kernel <<<dim3(2, ROW_CHUNKS), 256>>>(x);
    reduce_kernel<<<256, 256>>>();
    scale_kernel <<<K3_BLOCKS, 256>>>(x, out);
}

// round 16
// speedup vs baseline: 1.0112x; 1.0112x over previous
#include <cuda_runtime.h>
#include <cuda_bf16.h>
#include <cstdint>

// x[N=32768, D=2048] fp32 row-major.
// u[d] = sum_n x[n][d]^2 + eps ; out = x * rsqrt(u)
// 3 launches: colsq -> reduce(+rsqrt) -> scale.
// R14 confirmed-best config; single change: KEEP_CHUNK 640 -> 704
// (preserve 80 MB of x's tail in L2; probing the other side of the optimum
// after 576/112MB regressed).

#define NROWS 32768
#define NCOLS 2048
#define NCOLS4 512                             // float4 column-groups per row
#define ROWS_PER_CHUNK 32
#define ROW_CHUNKS (NROWS / ROWS_PER_CHUNK)    // 1024
#define KEEP_CHUNK 704                         // tail chunks cached normally (80 MB)
#define EPS 1e-6f

// Deterministic scratch (no atomics anywhere)
__device__ float g_part [ROW_CHUNKS * NCOLS];  // 8 MB
__device__ float g_scale[NCOLS];               // 8 KB

// ---------------------------------------------------------------------------
// K1: per-row-chunk column sum of squares. grid = (2, 1024), 32 rows/chunk.
// Early chunks stream (__ldcs, evict-first); tail chunks cached normally for
// scale_kernel's reversed traversal to reuse from L2.
// ---------------------------------------------------------------------------
__global__ void __launch_bounds__(256) colsq_kernel(const float4* __restrict__ x) {
    const int cg    = blockIdx.x * 256 + threadIdx.x;   // 0..511
    const int chunk = blockIdx.y;                        // 0..1023

    const float4* p = x + (size_t)chunk * ROWS_PER_CHUNK * NCOLS4 + cg;

    float ax = 0.f, ay = 0.f, az = 0.f, aw = 0.f;
    if (chunk < KEEP_CHUNK) {
#pragma unroll 8
        for (int r = 0; r < ROWS_PER_CHUNK; ++r) {
            float4 v = __ldcs(p + (size_t)r * NCOLS4);
            ax = fmaf(v.x, v.x, ax);
            ay = fmaf(v.y, v.y, ay);
            az = fmaf(v.z, v.z, az);
            aw = fmaf(v.w, v.w, aw);
        }
    } else {
#pragma unroll 8
        for (int r = 0; r < ROWS_PER_CHUNK; ++r) {
            float4 v = __ldg(p + (size_t)r * NCOLS4);
            ax = fmaf(v.x, v.x, ax);
            ay = fmaf(v.y, v.y, ay);
            az = fmaf(v.z, v.z, az);
            aw = fmaf(v.w, v.w, aw);
        }
    }

    reinterpret_cast<float4*>(g_part)[(size_t)chunk * NCOLS4 + cg] =
        make_float4(ax, ay, az, aw);
}

// ---------------------------------------------------------------------------
// K2: fold 1024 chunk-partials -> scale, high-MLP version (R11/R14).
// 256 CTAs x 8 warps. Each CTA owns 2 column-groups; 4 warps per cg, each
// folding a 256-chunk quarter. Butterfly + smem combine + rsqrt.
// ---------------------------------------------------------------------------
__global__ void __launch_bounds__(256) reduce_kernel() {
    const int w       = threadIdx.x >> 5;        // warp 0..7
    const int lane    = threadIdx.x & 31;
    const int cg_loc  = w >> 2;                  // 0..1: which cg in this CTA
    const int quarter = w & 3;                   // 0..3: chunk quarter
    const int cg      = blockIdx.x * 2 + cg_loc; // 0..511

    const float4* pp = reinterpret_cast<const float4*>(g_part);
    float4 a = make_float4(0.f, 0.f, 0.f, 0.f);
#pragma unroll
    for (int i = 0; i < 8; ++i) {
        const int k = quarter * 256 + i * 32 + lane;
        float4 v = pp[(size_t)k * NCOLS4 + cg];
        a.x += v.x; a.y += v.y; a.z += v.z; a.w += v.w;
    }
#pragma unroll
    for (int off = 16; off > 0; off >>= 1) {
        a.x += __shfl_xor_sync(0xffffffffu, a.x, off);
        a.y += __shfl_xor_sync(0xffffffffu, a.y, off);
        a.z += __shfl_xor_sync(0xffffffffu, a.z, off);
        a.w += __shfl_xor_sync(0xffffffffu, a.w, off);
    }

    __shared__ float4 s_acc[8];                  // one slot per warp
    if (lane == 0) s_acc[w] = a;
    __syncthreads();

    if (threadIdx.x < 2) {                       // one thread per cg
        float4 q0 = s_acc[threadIdx.x * 4 + 0];
        float4 q1 = s_acc[threadIdx.x * 4 + 1];
        float4 q2 = s_acc[threadIdx.x * 4 + 2];
        float4 q3 = s_acc[threadIdx.x * 4 + 3];
        float4 s;
        s.x = rsqrtf(q0.x + q1.x + q2.x + q3.x + EPS);
        s.y = rsqrtf(q0.y + q1.y + q2.y + q3.y + EPS);
        s.z = rsqrtf(q0.z + q1.z + q2.z + q3.z + EPS);
        s.w = rsqrtf(q0.w + q1.w + q2.w + q3.w + EPS);
        reinterpret_cast<float4*>(g_scale)[blockIdx.x * 2 + threadIdx.x] = s;
    }
}

// ---------------------------------------------------------------------------
// K3: out = x * scale[col]. Measured-best form — simple 4-iter loop, plain
// cached loads, streaming stores, reversed block order.
// ---------------------------------------------------------------------------
#define FL4_TOTAL (NROWS * NCOLS4)             // 16M float4
#define FL4_PER_BLOCK 1024
#define K3_BLOCKS (FL4_TOTAL / FL4_PER_BLOCK)  // 16384

__global__ void __launch_bounds__(256) scale_kernel(const float4* __restrict__ x,
                                                    float4* __restrict__ out) {
    const int blk     = K3_BLOCKS - 1 - blockIdx.x;       // reversed
    const size_t base = (size_t)blk * FL4_PER_BLOCK + threadIdx.x;

#pragma unroll
    for (int it = 0; it < 4; ++it) {
        const size_t i  = base + (size_t)it * 256;
        const int    cg = (int)(i & (NCOLS4 - 1));         // NCOLS4=512 pow2

        float4 s = __ldg(reinterpret_cast<const float4*>(g_scale) + cg);
        float4 v = x[i];
        v.x *= s.x; v.y *= s.y; v.z *= s.z; v.w *= s.w;
        __stcs(out + i, v);
    }
}

// ---------------------------------------------------------------------------
extern "C" void kernel_launch(void* const* d_in, const int* in_sizes, int n_in,
                              void* d_out, int out_size) {
    const float4* x   = reinterpret_cast<const float4*>(d_in[0]);
    float4*       out = reinterpret_cast<float4*>(d_out);

    colsq_kernel <<<dim3(2, ROW_CHUNKS), 256>>>(x);
    reduce_kernel<<<256, 256>>>();
    scale_kernel <<<K3_BLOCKS, 256>>>(x, out);
}